// round 1
// baseline (speedup 1.0000x reference)
#include <cuda_runtime.h>
#include <cstdint>

#define Bb   64
#define Tt   1024
#define Ee   512
#define Vv   256
#define NBLK 128

typedef unsigned long long u64;

// ---------------- device scratch (static: no runtime allocation) ----------------
__device__ float    g_P[Vv * Ee];                 // P[v][o] = emb[v]·w_x[o] + b_cell[o]   (512 KB)
__device__ float    g_hs[(size_t)Tt * Bb * Ee];   // hs[t][b][e]                            (128 MB)
__device__ unsigned g_bar[Tt];                    // per-step barrier counters

// ---------------- packed f32x2 helpers ----------------
__device__ __forceinline__ u64 fma2(u64 a, u64 b, u64 c) {
    u64 d;
    asm("fma.rn.f32x2 %0, %1, %2, %3;" : "=l"(d) : "l"(a), "l"(b), "l"(c));
    return d;
}
__device__ __forceinline__ float lo32(u64 v) { return __uint_as_float((unsigned)(v & 0xffffffffull)); }
__device__ __forceinline__ float hi32(u64 v) { return __uint_as_float((unsigned)(v >> 32)); }

// ---------------- barrier counter reset (each replay) ----------------
__global__ void zero_bar_kernel() {
    for (int i = threadIdx.x; i < Tt; i += 256) g_bar[i] = 0;
}

// ---------------- P = emb @ w_x^T + b_cell   (256 x 512, K=512) ----------------
__global__ void p_gemm_kernel(const float* __restrict__ emb,
                              const float* __restrict__ w_cell,
                              const float* __restrict__ b_cell) {
    __shared__ float As[64][16];   // [row][k]
    __shared__ float Bs[16][64];   // [k][col]
    int tid = threadIdx.x;
    int rbase = blockIdx.x * 64;   // v
    int cbase = blockIdx.y * 64;   // o
    int ti = tid >> 4, tj = tid & 15;
    int arow = tid >> 2, ac4 = (tid & 3) * 4;
    float acc[4][4] = {};

    for (int k0 = 0; k0 < Ee; k0 += 16) {
        float4 av = *(const float4*)&emb[(rbase + arow) * Ee + k0 + ac4];
        *(float4*)&As[arow][ac4] = av;
        // w_x[o][e] = w_cell[o*1024 + e]
        float4 bv = *(const float4*)&w_cell[(size_t)(cbase + arow) * (2 * Ee) + k0 + ac4];
        Bs[ac4 + 0][arow] = bv.x; Bs[ac4 + 1][arow] = bv.y;
        Bs[ac4 + 2][arow] = bv.z; Bs[ac4 + 3][arow] = bv.w;
        __syncthreads();
#pragma unroll
        for (int kk = 0; kk < 16; kk++) {
            float a0 = As[ti * 4 + 0][kk];
            float a1 = As[ti * 4 + 1][kk];
            float a2 = As[ti * 4 + 2][kk];
            float a3 = As[ti * 4 + 3][kk];
            float4 b4 = *(const float4*)&Bs[kk][tj * 4];
            acc[0][0] = fmaf(a0, b4.x, acc[0][0]); acc[0][1] = fmaf(a0, b4.y, acc[0][1]);
            acc[0][2] = fmaf(a0, b4.z, acc[0][2]); acc[0][3] = fmaf(a0, b4.w, acc[0][3]);
            acc[1][0] = fmaf(a1, b4.x, acc[1][0]); acc[1][1] = fmaf(a1, b4.y, acc[1][1]);
            acc[1][2] = fmaf(a1, b4.z, acc[1][2]); acc[1][3] = fmaf(a1, b4.w, acc[1][3]);
            acc[2][0] = fmaf(a2, b4.x, acc[2][0]); acc[2][1] = fmaf(a2, b4.y, acc[2][1]);
            acc[2][2] = fmaf(a2, b4.z, acc[2][2]); acc[2][3] = fmaf(a2, b4.w, acc[2][3]);
            acc[3][0] = fmaf(a3, b4.x, acc[3][0]); acc[3][1] = fmaf(a3, b4.y, acc[3][1]);
            acc[3][2] = fmaf(a3, b4.z, acc[3][2]); acc[3][3] = fmaf(a3, b4.w, acc[3][3]);
        }
        __syncthreads();
    }
#pragma unroll
    for (int ii = 0; ii < 4; ii++) {
        int r = rbase + ti * 4 + ii;
        int c = cbase + tj * 4;
        float4 o;
        o.x = acc[ii][0] + b_cell[c + 0];
        o.y = acc[ii][1] + b_cell[c + 1];
        o.z = acc[ii][2] + b_cell[c + 2];
        o.w = acc[ii][3] + b_cell[c + 3];
        *(float4*)&g_P[r * Ee + c] = o;
    }
}

// ---------------- persistent recurrence kernel ----------------
// 128 CTAs = 8 batch-tiles (8 rows each) x 16 col-tiles (32 cols each).
// w_h slice lives in registers (32 x f32x2 per thread, preloaded once).
__global__ void __launch_bounds__(256, 1)
rnn_rec_kernel(const int* __restrict__ x,
               const float* __restrict__ w_cell,
               const float* __restrict__ h0) {
    __shared__ __align__(16) float hsm[8 * Ee];     // 16 KB: h tile (8 batch x 512)
    __shared__ float psum[8 * 8 * 32];              // 8 KB:  [b][kslice][c]

    int tid = threadIdx.x;
    int bid = blockIdx.x;
    int io = bid & 15, ib = bid >> 4;
    int obase = io * 32, bbase = ib * 8;
    int c  = tid & 31;       // output col within tile
    int ks = tid >> 5;       // k-slice 0..7 (64 k each)
    int k0 = ks * 64;

    // preload w_h slice: w_h[o][e] = w_cell[o*1024 + 512 + e]
    u64 wreg[32];
    {
        const u64* wp = (const u64*)w_cell;
        int base = ((obase + c) * (2 * Ee) + Ee + k0) >> 1;
#pragma unroll
        for (int j = 0; j < 32; j++) wreg[j] = wp[base + j];
    }

    for (int t = 0; t < Tt; t++) {
        // ---- load previous h tile (8 x 512 fp32 = 16 KB) ----
        if (t == 0) {
            const float4* h04 = (const float4*)h0;
#pragma unroll
            for (int q = 0; q < 4; q++) {
                int idx = tid + q * 256;          // float4 index 0..1023
                int e4  = idx & 127;              // column group within row
                ((float4*)hsm)[idx] = h04[e4];
            }
        } else {
            const float4* hp4 = (const float4*)(g_hs + ((size_t)(t - 1) * Bb + bbase) * Ee);
#pragma unroll
            for (int q = 0; q < 4; q++) {
                int idx = tid + q * 256;
                ((float4*)hsm)[idx] = __ldcg(&hp4[idx]);
            }
        }
        __syncthreads();

        // ---- partial dot products: each thread covers 64 k for one col, all 8 batches ----
#pragma unroll 1
        for (int b = 0; b < 8; b++) {
            const u64* hp = (const u64*)(hsm + b * Ee + k0);
            u64 a0 = 0ull, a1 = 0ull;
#pragma unroll
            for (int q = 0; q < 32; q += 2) {
                a0 = fma2(hp[q],     wreg[q],     a0);
                a1 = fma2(hp[q + 1], wreg[q + 1], a1);
            }
            psum[(b * 8 + ks) * 32 + c] = lo32(a0) + hi32(a0) + lo32(a1) + hi32(a1);
        }
        __syncthreads();

        // ---- reduce 8 partials, add table entry, tanh, store h_t ----
        {
            int b  = tid >> 5;
            int cc = tid & 31;
            float s = 0.f;
#pragma unroll
            for (int q = 0; q < 8; q++) s += psum[(b * 8 + q) * 32 + cc];
            int bg = bbase + b;
            int xv = __ldg(&x[bg * Tt + t]);
            float val = s + g_P[xv * Ee + obase + cc];
            g_hs[((size_t)t * Bb + bg) * Ee + obase + cc] = tanhf(val);
        }

        // ---- grid-wide barrier for step t ----
        __threadfence();
        __syncthreads();
        if (tid == 0) {
            atomicAdd(&g_bar[t], 1u);
            while (*(volatile unsigned*)&g_bar[t] < NBLK) { }
        }
        __syncthreads();
    }
}

// ---------------- head GEMM: out[b][t][v] = hs[t][b][:]·w_head[v][:] + b_head[v] ----------------
__global__ void head_gemm_kernel(const float* __restrict__ w_head,
                                 const float* __restrict__ b_head,
                                 float* __restrict__ out) {
    __shared__ float As[64][16];   // [row][k]   rows r = t*B + b
    __shared__ float Bs[16][64];   // [k][col]
    int tid = threadIdx.x;
    int rbase = blockIdx.x * 64;
    int cbase = blockIdx.y * 64;
    int ti = tid >> 4, tj = tid & 15;
    int arow = tid >> 2, ac4 = (tid & 3) * 4;
    float acc[4][4] = {};

    for (int k0 = 0; k0 < Ee; k0 += 16) {
        float4 av = *(const float4*)&g_hs[(size_t)(rbase + arow) * Ee + k0 + ac4];
        *(float4*)&As[arow][ac4] = av;
        float4 bv = *(const float4*)&w_head[(size_t)(cbase + arow) * Ee + k0 + ac4];
        Bs[ac4 + 0][arow] = bv.x; Bs[ac4 + 1][arow] = bv.y;
        Bs[ac4 + 2][arow] = bv.z; Bs[ac4 + 3][arow] = bv.w;
        __syncthreads();
#pragma unroll
        for (int kk = 0; kk < 16; kk++) {
            float a0 = As[ti * 4 + 0][kk];
            float a1 = As[ti * 4 + 1][kk];
            float a2 = As[ti * 4 + 2][kk];
            float a3 = As[ti * 4 + 3][kk];
            float4 b4 = *(const float4*)&Bs[kk][tj * 4];
            acc[0][0] = fmaf(a0, b4.x, acc[0][0]); acc[0][1] = fmaf(a0, b4.y, acc[0][1]);
            acc[0][2] = fmaf(a0, b4.z, acc[0][2]); acc[0][3] = fmaf(a0, b4.w, acc[0][3]);
            acc[1][0] = fmaf(a1, b4.x, acc[1][0]); acc[1][1] = fmaf(a1, b4.y, acc[1][1]);
            acc[1][2] = fmaf(a1, b4.z, acc[1][2]); acc[1][3] = fmaf(a1, b4.w, acc[1][3]);
            acc[2][0] = fmaf(a2, b4.x, acc[2][0]); acc[2][1] = fmaf(a2, b4.y, acc[2][1]);
            acc[2][2] = fmaf(a2, b4.z, acc[2][2]); acc[2][3] = fmaf(a2, b4.w, acc[2][3]);
            acc[3][0] = fmaf(a3, b4.x, acc[3][0]); acc[3][1] = fmaf(a3, b4.y, acc[3][1]);
            acc[3][2] = fmaf(a3, b4.z, acc[3][2]); acc[3][3] = fmaf(a3, b4.w, acc[3][3]);
        }
        __syncthreads();
    }
#pragma unroll
    for (int ii = 0; ii < 4; ii++) {
        int r  = rbase + ti * 4 + ii;      // r = t*B + b
        int bb = r & (Bb - 1);
        int tt = r >> 6;
        int cc = cbase + tj * 4;
        float4 o;
        o.x = acc[ii][0] + b_head[cc + 0];
        o.y = acc[ii][1] + b_head[cc + 1];
        o.z = acc[ii][2] + b_head[cc + 2];
        o.w = acc[ii][3] + b_head[cc + 3];
        *(float4*)&out[(size_t)bb * (Tt * Vv) + (size_t)tt * Vv + cc] = o;
    }
}

// ---------------- launch ----------------
extern "C" void kernel_launch(void* const* d_in, const int* in_sizes, int n_in,
                              void* d_out, int out_size) {
    const int*   x      = (const int*)  d_in[0];
    const float* emb    = (const float*)d_in[1];
    const float* w_cell = (const float*)d_in[2];
    const float* b_cell = (const float*)d_in[3];
    const float* w_head = (const float*)d_in[4];
    const float* b_head = (const float*)d_in[5];
    const float* h0     = (const float*)d_in[6];
    float* out = (float*)d_out;

    zero_bar_kernel<<<1, 256>>>();
    p_gemm_kernel<<<dim3(Vv / 64, Ee / 64), 256>>>(emb, w_cell, b_cell);
    rnn_rec_kernel<<<NBLK, 256>>>(x, w_cell, h0);
    head_gemm_kernel<<<dim3((Bb * Tt) / 64, Vv / 64), 256>>>(w_head, b_head, out);
}